// round 10
// baseline (speedup 1.0000x reference)
#include <cuda_runtime.h>
#include <cstdint>

// adj: (B=2, N=2048, N=2048, F=16) fp32
// f=8, stride=4 -> S=511 window starts; NOFF=56 off-diagonal offsets
// out: (B, S, 56*16) fp32 = 915712 floats = 228928 float4
//
// One thread per HALF-element (2x float4 = 8 floats). MLP=2 per thread,
// 114464 threads -> 448 blocks of 256 -> ~24 warps/SM (vs 12 in R3, vs
// MLP=1 in R2). Output float4 index = tid*2 (+0,+1): fully coalesced.

namespace {
constexpr int B = 2;
constexpr int N = 2048;
constexpr int STRIDE = 4;
constexpr int S = 511;
constexpr int NOFF = 56;
constexpr int TOTAL_PAIRS = B * S * NOFF * 2;   // 114464
}

__global__ void __launch_bounds__(256)
sparse_diag_unfold_kernel(const float4* __restrict__ adj,
                          float4* __restrict__ out) {
    int tid = blockIdx.x * blockDim.x + threadIdx.x;
    if (tid >= TOTAL_PAIRS) return;

    int half = tid & 1;          // which 8-float half of the 16-float element
    int e    = tid >> 1;         // element index: (b*S + s)*NOFF + off
    int off  = e % NOFF;
    int bs   = e / NOFF;
    int s    = bs % S;
    int b    = bs / S;

    int local = off + 1 + (off >> 3);   // skip diagonal (local % 9 == 0)
    int ii = local >> 3;
    int jj = local & 7;

    int row = s * STRIDE + ii;
    int col = s * STRIDE + jj;

    // float4 index into adj: element base has 4 float4; this thread takes 2.
    long long src = ((((long long)b * N + row) * N + col) << 2) + (half << 1);
    long long dst = (long long)tid << 1;

    float4 v0 = adj[src + 0];
    float4 v1 = adj[src + 1];

    out[dst + 0] = v0;
    out[dst + 1] = v1;
}

extern "C" void kernel_launch(void* const* d_in, const int* in_sizes, int n_in,
                              void* d_out, int out_size) {
    const float4* adj = (const float4*)d_in[0];
    float4* out = (float4*)d_out;

    const int threads = 256;
    const int blocks = (TOTAL_PAIRS + threads - 1) / threads;   // 448
    sparse_diag_unfold_kernel<<<blocks, threads>>>(adj, out);
}

// round 12
// speedup vs baseline: 1.0419x; 1.0419x over previous
#include <cuda_runtime.h>
#include <cstdint>

// adj: (B=2, N=2048, N=2048, F=16) fp32
// f=8, stride=4 -> S=511 window starts; NOFF=56 off-diagonal offsets
// out: (B, S, 56*16) fp32 = 915712 floats
//
// One thread per HALF-element (8 floats = 32 bytes), moved with a single
// 256-bit ld.global.nc.v8.f32 + st.global.v8.f32 (sm_100+ feature).
// 114464 threads -> 448 blocks of 256 -> ~24 warps/SM.
// src element base is 64B-aligned, half offset is 32B -> both ops 32B-aligned.
// dst = tid*32B -> fully coalesced, 32B-aligned.

namespace {
constexpr int B = 2;
constexpr int N = 2048;
constexpr int STRIDE = 4;
constexpr int S = 511;
constexpr int NOFF = 56;
constexpr int TOTAL_HALVES = B * S * NOFF * 2;   // 114464
}

__global__ void __launch_bounds__(256)
sparse_diag_unfold_kernel(const float* __restrict__ adj,
                          float* __restrict__ out) {
    int tid = blockIdx.x * blockDim.x + threadIdx.x;
    if (tid >= TOTAL_HALVES) return;

    int half = tid & 1;          // which 32B half of the 64B element
    int e    = tid >> 1;         // element index: (b*S + s)*NOFF + off
    int off  = e % NOFF;
    int bs   = e / NOFF;
    int s    = bs % S;
    int b    = bs / S;

    int local = off + 1 + (off >> 3);   // skip diagonal (local % 9 == 0)
    int ii = local >> 3;
    int jj = local & 7;

    int row = s * STRIDE + ii;
    int col = s * STRIDE + jj;

    // float index into adj: element base (16 floats) + half*8
    long long src_f = ((((long long)b * N + row) * N + col) << 4) + (half << 3);
    long long dst_f = (long long)tid << 3;

    const float* sp = adj + src_f;
    float* dp = out + dst_f;

    float r0, r1, r2, r3, r4, r5, r6, r7;
    asm volatile(
        "ld.global.nc.v8.f32 {%0, %1, %2, %3, %4, %5, %6, %7}, [%8];"
        : "=f"(r0), "=f"(r1), "=f"(r2), "=f"(r3),
          "=f"(r4), "=f"(r5), "=f"(r6), "=f"(r7)
        : "l"(sp));
    asm volatile(
        "st.global.v8.f32 [%0], {%1, %2, %3, %4, %5, %6, %7, %8};"
        :: "l"(dp),
           "f"(r0), "f"(r1), "f"(r2), "f"(r3),
           "f"(r4), "f"(r5), "f"(r6), "f"(r7)
        : "memory");
}

extern "C" void kernel_launch(void* const* d_in, const int* in_sizes, int n_in,
                              void* d_out, int out_size) {
    const float* adj = (const float*)d_in[0];
    float* out = (float*)d_out;

    const int threads = 256;
    const int blocks = (TOTAL_HALVES + threads - 1) / threads;   // 448
    sparse_diag_unfold_kernel<<<blocks, threads>>>(adj, out);
}

// round 14
// speedup vs baseline: 1.0769x; 1.0337x over previous
#include <cuda_runtime.h>
#include <cstdint>

// adj: (B=2, N=2048, N=2048, F=16) fp32
// f=8, stride=4 -> S=511 window starts; NOFF=56 off-diagonal offsets
// out: (B, S, 56*16) fp32 = 915712 floats = 228928 float4
//
// One block per (b, s) window: 224 threads = 56 offsets x 4 quads.
//   off  = tid >> 2, quad = tid & 3     (no division anywhere)
//   local = off + 1 + off/8; ii = local/8; jj = local%8   (shifts only)
//   row = 4s + ii, col = 4s + jj
// dst float4 index = blockIdx.x * 224 + tid  -> block writes 3.5KB contiguous.
// Grid = 1022 blocks x 7 warps -> ~49 warps/SM resident (occ ~75%).

namespace {
constexpr int N = 2048;
constexpr int S = 511;
constexpr int STRIDE = 4;
constexpr int NOFF = 56;
constexpr int TPB = NOFF * 4;          // 224 threads per block
}

__global__ void __launch_bounds__(TPB)
sparse_diag_unfold_kernel(const float4* __restrict__ adj,
                          float4* __restrict__ out) {
    int tid = threadIdx.x;              // 0..223
    int bs  = blockIdx.x;               // b*S + s  (0..1021)

    int quad = tid & 3;
    int off  = tid >> 2;                // 0..55

    // b*S + s decomposition: b = bs >= S ? 1 : 0  (B=2 only)
    int b = (bs >= S) ? 1 : 0;
    int s = bs - b * S;

    int local = off + 1 + (off >> 3);   // skip diagonal (local % 9 == 0)
    int ii = local >> 3;
    int jj = local & 7;

    int row = s * STRIDE + ii;
    int col = s * STRIDE + jj;

    // float4 index into adj: (((b*N + row)*N + col) * 16 + quad*4) / 4
    // max = 2*2048*2048*4 = 33,554,432  -> fits in 32-bit
    unsigned src = ((((unsigned)b * N + row) * N + col) << 2) + quad;
    unsigned dst = (unsigned)bs * TPB + tid;

    out[dst] = __ldg(&adj[src]);
}

extern "C" void kernel_launch(void* const* d_in, const int* in_sizes, int n_in,
                              void* d_out, int out_size) {
    const float4* adj = (const float4*)d_in[0];
    float4* out = (float4*)d_out;

    const int blocks = 2 * S;           // 1022 blocks, one per (b, s)
    sparse_diag_unfold_kernel<<<blocks, TPB>>>(adj, out);
}